// round 3
// baseline (speedup 1.0000x reference)
#include <cuda_runtime.h>
#include <math.h>

// Problem constants
#define NTOK 49          // tokens per window (7x7)
#define MPAD 56          // padded token rows (14 warps x 4 rows)
#define DIMX 512         // model dim
#define NHEAD 8
#define DHEAD 32
#define DINNER 256       // NHEAD*DHEAD
#define QKVW 768         // 3*DINNER
#define NTHREADS 512
#define NWARPS 16
#define GWARPS 14        // warps doing GEMM rows (14*4 = 56)
#define RROWS 4          // register rows per warp
#define KC 32            // k-chunk for weight staging

// Shared memory layout (float offsets)
#define XS_OFF 0                     // 56*512 = 28672
#define AO_OFF 28672                 // 56*256 = 14336 -> 43008
#define Q_OFF  43008                 // 56*33  = 1848  -> 44856
#define K_OFF  44856                 // 1848 -> 46704
#define V_OFF  46704                 // 1848 -> 48552
#define PR_OFF 48552                 // 16*52 = 832 -> 49384
#define RC_OFF 49384                 // 49*32 = 1568 -> 50952
#define RS_OFF 50952                 // 1568 -> 52520
#define WT_OFF 52520                 // max(32*96, 32*128)=4096 -> 56616
#define SC_OFF 56616                 // 56 -> 56672
#define G_OFF  56672                 // 56*8 = 448 -> 57120
#define SMEM_FLOATS 57120            // 228480 bytes

__global__ __launch_bounds__(NTHREADS, 1)
void fused_win_attn_kernel(const float* __restrict__ x,
                           const float* __restrict__ rotary,
                           const float* __restrict__ gamma,
                           const float* __restrict__ w_qkv,
                           const float* __restrict__ w_g,
                           const float* __restrict__ b_g,
                           const float* __restrict__ w_out,
                           float* __restrict__ out)
{
    extern __shared__ float sm[];
    float* xs = sm + XS_OFF;

    const int tid  = threadIdx.x;
    const int lane = tid & 31;
    const int warp = tid >> 5;
    const long win = blockIdx.x;
    const float* xw = x + win * (long)(NTOK * DIMX);

    // ---------------- Phase 0: load x*gamma (pad rows zero) ----------------
    for (int idx = tid; idx < MPAD * DIMX / 4; idx += NTHREADS) {
        int r  = idx / (DIMX / 4);
        int k4 = (idx % (DIMX / 4)) * 4;
        float4 v = make_float4(0.f, 0.f, 0.f, 0.f);
        if (r < NTOK) {
            float4 xv = *(const float4*)(xw + r * DIMX + k4);
            float4 gm = *(const float4*)(gamma + k4);
            v.x = xv.x * gm.x; v.y = xv.y * gm.y;
            v.z = xv.z * gm.z; v.w = xv.w * gm.w;
        }
        *(float4*)(xs + r * DIMX + k4) = v;
    }

    // row norms from raw x (reference: norm of x BEFORE gamma)
    for (int r = warp; r < NTOK; r += NWARPS) {
        float ss = 0.f;
        for (int k = lane * 4; k < DIMX; k += 128) {
            float4 xv = *(const float4*)(xw + r * DIMX + k);
            ss += xv.x * xv.x + xv.y * xv.y + xv.z * xv.z + xv.w * xv.w;
        }
        #pragma unroll
        for (int o = 16; o; o >>= 1) ss += __shfl_xor_sync(0xffffffffu, ss, o);
        if (lane == 0)
            sm[SC_OFF + r] = 22.627416997969522f / fmaxf(sqrtf(ss), 1e-12f); // sqrt(512)/max(||x||,eps)
    }

    // rope tables
    for (int idx = tid; idx < NTOK * DHEAD; idx += NTHREADS) {
        float re = rotary[idx];
        sm[RC_OFF + idx] = cosf(re);
        sm[RS_OFF + idx] = sinf(re);
    }
    // zero padded rows of attention-output accumulator
    for (int idx = tid; idx < (MPAD - NTOK) * DINNER; idx += NTHREADS)
        sm[AO_OFF + NTOK * DINNER + idx] = 0.f;
    __syncthreads();

    // apply row scale -> xs now holds xn
    for (int idx = tid; idx < NTOK * DIMX; idx += NTHREADS) {
        int r = idx >> 9;
        xs[idx] *= sm[SC_OFF + r];
    }
    __syncthreads();

    // ---------------- gating g = sigmoid(xn @ w_g + b_g) ----------------
    for (int r = warp; r < NTOK; r += NWARPS) {
        float acc[NHEAD];
        #pragma unroll
        for (int h = 0; h < NHEAD; h++) acc[h] = 0.f;
        for (int k = lane; k < DIMX; k += 32) {
            float xv = xs[r * DIMX + k];
            float4 wg0 = *(const float4*)(w_g + k * NHEAD);
            float4 wg1 = *(const float4*)(w_g + k * NHEAD + 4);
            acc[0] += xv * wg0.x; acc[1] += xv * wg0.y;
            acc[2] += xv * wg0.z; acc[3] += xv * wg0.w;
            acc[4] += xv * wg1.x; acc[5] += xv * wg1.y;
            acc[6] += xv * wg1.z; acc[7] += xv * wg1.w;
        }
        #pragma unroll
        for (int h = 0; h < NHEAD; h++) {
            #pragma unroll
            for (int o = 16; o; o >>= 1)
                acc[h] += __shfl_xor_sync(0xffffffffu, acc[h], o);
        }
        if (lane == 0) {
            #pragma unroll
            for (int h = 0; h < NHEAD; h++)
                sm[G_OFF + r * NHEAD + h] = 1.f / (1.f + __expf(-(acc[h] + b_g[h])));
        }
    }

    const float attn_scale = 0.17677669529663687f; // 32^-0.5

    // ---------------- per-head: QKV GEMM + RoPE + attention ----------------
    for (int h = 0; h < NHEAD; h++) {
        float aq[RROWS], ak[RROWS], av[RROWS];
        #pragma unroll
        for (int rr = 0; rr < RROWS; rr++) { aq[rr] = 0.f; ak[rr] = 0.f; av[rr] = 0.f; }

        for (int k0 = 0; k0 < DIMX; k0 += KC) {
            __syncthreads();
            // stage w tile [KC][96]: cols 0-31=q, 32-63=k, 64-95=v for head h
            for (int idx = tid; idx < KC * 96; idx += NTHREADS) {
                int kk = idx / 96, c = idx % 96;
                int gcol = (c < 32) ? (h * 32 + c)
                         : (c < 64) ? (256 + h * 32 + c - 32)
                                    : (512 + h * 32 + c - 64);
                sm[WT_OFF + idx] = w_qkv[(k0 + kk) * QKVW + gcol];
            }
            __syncthreads();
            if (warp < GWARPS) {
                const int r0 = warp * RROWS;
                #pragma unroll
                for (int kk4 = 0; kk4 < KC; kk4 += 4) {
                    float4 xv[RROWS];
                    #pragma unroll
                    for (int rr = 0; rr < RROWS; rr++)
                        xv[rr] = *(const float4*)(xs + (r0 + rr) * DIMX + k0 + kk4);
                    #pragma unroll
                    for (int t = 0; t < 4; t++) {
                        float wq = sm[WT_OFF + (kk4 + t) * 96 + lane];
                        float wk = sm[WT_OFF + (kk4 + t) * 96 + 32 + lane];
                        float wv = sm[WT_OFF + (kk4 + t) * 96 + 64 + lane];
                        #pragma unroll
                        for (int rr = 0; rr < RROWS; rr++) {
                            float xe = (t == 0) ? xv[rr].x : (t == 1) ? xv[rr].y
                                     : (t == 2) ? xv[rr].z : xv[rr].w;
                            aq[rr] += xe * wq;
                            ak[rr] += xe * wk;
                            av[rr] += xe * wv;
                        }
                    }
                }
            }
        }

        // RoPE in registers via pair shuffle, store q/k/v tiles
        if (warp < GWARPS) {
            const int r0 = warp * RROWS;
            #pragma unroll
            for (int rr = 0; rr < RROWS; rr++) {
                int r = r0 + rr;
                float qv = aq[rr], kv = ak[rr];
                float qp = __shfl_xor_sync(0xffffffffu, qv, 1);
                float kp = __shfl_xor_sync(0xffffffffu, kv, 1);
                float qo = 0.f, ko = 0.f;
                if (r < NTOK) {
                    float c = sm[RC_OFF + r * DHEAD + lane];
                    float s = sm[RS_OFF + r * DHEAD + lane];
                    float sgn = (lane & 1) ? 1.f : -1.f;
                    qo = qv * c + sgn * qp * s;
                    ko = kv * c + sgn * kp * s;
                }
                sm[Q_OFF + r * 33 + lane] = qo;
                sm[K_OFF + r * 33 + lane] = ko;
                sm[V_OFF + r * 33 + lane] = (r < NTOK) ? av[rr] : 0.f;
            }
        }
        __syncthreads();

        // attention: warp-per-query-row, lane covers j and j+32
        for (int i = warp; i < NTOK; i += NWARPS) {
            int j1 = lane, j2 = lane + 32;
            int j2c = (j2 < NTOK) ? j2 : 0;
            float s1 = 0.f, s2 = 0.f;
            #pragma unroll
            for (int d = 0; d < DHEAD; d++) {
                float qv = sm[Q_OFF + i * 33 + d];
                s1 += qv * sm[K_OFF + j1 * 33 + d];
                s2 += qv * sm[K_OFF + j2c * 33 + d];
            }
            s1 *= attn_scale; s2 *= attn_scale;
            float m2v = (j2 < NTOK) ? s2 : -1e30f;
            float mx = fmaxf(s1, m2v);
            #pragma unroll
            for (int o = 16; o; o >>= 1)
                mx = fmaxf(mx, __shfl_xor_sync(0xffffffffu, mx, o));
            float e1 = __expf(s1 - mx);
            float e2 = (j2 < NTOK) ? __expf(s2 - mx) : 0.f;
            float sum = e1 + e2;
            #pragma unroll
            for (int o = 16; o; o >>= 1)
                sum += __shfl_xor_sync(0xffffffffu, sum, o);
            float inv = __fdividef(1.f, sum);
            sm[PR_OFF + warp * 52 + j1] = e1 * inv;
            if (j2 < NTOK) sm[PR_OFF + warp * 52 + j2] = e2 * inv;
            __syncwarp();
            float acc = 0.f;
            #pragma unroll 7
            for (int j = 0; j < NTOK; j++)
                acc += sm[PR_OFF + warp * 52 + j] * sm[V_OFF + j * 33 + lane];
            acc *= sm[G_OFF + i * NHEAD + h];
            sm[AO_OFF + i * DINNER + h * DHEAD + lane] = acc;
            __syncwarp();
        }
        __syncthreads();
    }

    // ---------------- output projection: (56x256) @ (256x512) ----------------
    const long obase = win * (long)(NTOK * DIMX);
    for (int cb = 0; cb < 4; cb++) {
        float acc[RROWS][4];
        #pragma unroll
        for (int rr = 0; rr < RROWS; rr++)
            #pragma unroll
            for (int s = 0; s < 4; s++) acc[rr][s] = 0.f;

        for (int k0 = 0; k0 < DINNER; k0 += 32) {
            __syncthreads();
            for (int idx = tid; idx < 32 * 128; idx += NTHREADS) {
                int kk = idx >> 7, c = idx & 127;
                sm[WT_OFF + idx] = w_out[(k0 + kk) * DIMX + cb * 128 + c];
            }
            __syncthreads();
            if (warp < GWARPS) {
                const int r0 = warp * RROWS;
                #pragma unroll
                for (int kk4 = 0; kk4 < 32; kk4 += 4) {
                    float4 a4[RROWS];
                    #pragma unroll
                    for (int rr = 0; rr < RROWS; rr++)
                        a4[rr] = *(const float4*)(sm + AO_OFF + (r0 + rr) * DINNER + k0 + kk4);
                    #pragma unroll
                    for (int t = 0; t < 4; t++) {
                        float w0 = sm[WT_OFF + (kk4 + t) * 128 + lane];
                        float w1 = sm[WT_OFF + (kk4 + t) * 128 + 32 + lane];
                        float w2 = sm[WT_OFF + (kk4 + t) * 128 + 64 + lane];
                        float w3 = sm[WT_OFF + (kk4 + t) * 128 + 96 + lane];
                        #pragma unroll
                        for (int rr = 0; rr < RROWS; rr++) {
                            float xe = (t == 0) ? a4[rr].x : (t == 1) ? a4[rr].y
                                     : (t == 2) ? a4[rr].z : a4[rr].w;
                            acc[rr][0] += xe * w0;
                            acc[rr][1] += xe * w1;
                            acc[rr][2] += xe * w2;
                            acc[rr][3] += xe * w3;
                        }
                    }
                }
            }
        }
        if (warp < GWARPS) {
            const int r0 = warp * RROWS;
            #pragma unroll
            for (int rr = 0; rr < RROWS; rr++) {
                int r = r0 + rr;
                if (r < NTOK) {
                    float* op = out + obase + r * DIMX + cb * 128 + lane;
                    op[0]  = acc[rr][0];
                    op[32] = acc[rr][1];
                    op[64] = acc[rr][2];
                    op[96] = acc[rr][3];
                }
            }
        }
    }
}

extern "C" void kernel_launch(void* const* d_in, const int* in_sizes, int n_in,
                              void* d_out, int out_size)
{
    const float* x     = (const float*)d_in[0];
    const float* rot   = (const float*)d_in[1];
    const float* gamma = (const float*)d_in[2];
    const float* w_qkv = (const float*)d_in[3];
    const float* w_g   = (const float*)d_in[4];
    const float* b_g   = (const float*)d_in[5];
    const float* w_out = (const float*)d_in[6];

    int nwin = in_sizes[0] / (NTOK * DIMX);   // 2048 for this dataset
    size_t smem = SMEM_FLOATS * sizeof(float);
    cudaFuncSetAttribute(fused_win_attn_kernel,
                         cudaFuncAttributeMaxDynamicSharedMemorySize, (int)smem);
    fused_win_attn_kernel<<<nwin, NTHREADS, smem>>>(
        x, rot, gamma, w_qkv, w_g, b_g, w_out, (float*)d_out);
}

// round 15
// speedup vs baseline: 1.4827x; 1.4827x over previous
#include <cuda_runtime.h>
#include <math.h>

#define NTOK 49
#define DIMX 512
#define NHEAD 8
#define QKVW 768
#define NTHREADS 512

// smem strides (floats):
//   A-operand regions (XS, AO): stride ≡ 4 (mod 32) -> A-fragment loads conflict-free
//   B-operand regions (BQ, BO): stride ≡ 8 (mod 32) -> B-fragment loads conflict-free
#define XS_STR 516
#define BQ_STR 104
#define AO_STR 260
#define BO_STR 520
#define TIL_STR 33
#define TIL_SZ 1632

// smem layout (float offsets)
#define XS_OFF 0          // 56*516 = 28896 (xn tf32-rounded; rows 49..55 zero; overlaid by w_out stage later)
#define BQ_OFF 28896      // 32*104 = 3328
#define QT_OFF 32224      // 1632
#define KT_OFF 33856
#define VT_OFF 35488
#define AO_OFF 37120      // 56*260 = 14560
#define RC_OFF 51680      // 49*32
#define RS_OFF 53248
#define PR_OFF 54816      // 16*52
#define G_OFF  55648      // 49*8
#define SC_OFF 56040      // 56
#define SMEM_FLOATS 56096 // 224384 bytes

__device__ __forceinline__ unsigned tf32u(float f) {
    unsigned u; asm("cvt.rna.tf32.f32 %0, %1;" : "=r"(u) : "f"(f)); return u;
}
__device__ __forceinline__ float tf32f(float f) { return __uint_as_float(tf32u(f)); }

__device__ __forceinline__ void mma8(float* c,
                                     unsigned a0, unsigned a1, unsigned a2, unsigned a3,
                                     unsigned b0, unsigned b1) {
    asm volatile(
        "mma.sync.aligned.m16n8k8.row.col.f32.tf32.tf32.f32 "
        "{%0,%1,%2,%3},{%4,%5,%6,%7},{%8,%9},{%0,%1,%2,%3};"
        : "+f"(c[0]), "+f"(c[1]), "+f"(c[2]), "+f"(c[3])
        : "r"(a0), "r"(a1), "r"(a2), "r"(a3), "r"(b0), "r"(b1));
}

__global__ __launch_bounds__(NTHREADS, 1)
void fused_win_attn_tc(const float* __restrict__ x,
                       const float* __restrict__ rotary,
                       const float* __restrict__ gamma,
                       const float* __restrict__ w_qkv,
                       const float* __restrict__ w_g,
                       const float* __restrict__ b_g,
                       const float* __restrict__ w_out,
                       float* __restrict__ out)
{
    extern __shared__ float sm[];
    unsigned* smu = (unsigned*)sm;

    const int tid  = threadIdx.x;
    const int lane = tid & 31;
    const int warp = tid >> 5;
    const int gi   = lane >> 2;   // groupID 0..7
    const int tg   = lane & 3;    // thread-in-group 0..3
    const int mw   = warp >> 2;   // m-tile 0..3
    const int nw   = warp & 3;    // n-group 0..3
    const int m0   = mw * 16;
    const bool hi_ok = (mw < 3);  // rows m0+8+gi < 56 iff mw<3

    const long win = blockIdx.x;
    const float* xw = x + win * (long)(NTOK * DIMX);

    // ---------------- Phase 0 ----------------
    // row scales sc[r] = sqrt(512)/max(||x_r||, eps) from raw global x
    for (int r = warp; r < NTOK; r += 16) {
        float ss = 0.f;
        for (int k = lane * 4; k < DIMX; k += 128) {
            float4 xv = *(const float4*)(xw + r * DIMX + k);
            ss += xv.x * xv.x + xv.y * xv.y + xv.z * xv.z + xv.w * xv.w;
        }
        #pragma unroll
        for (int o = 16; o; o >>= 1) ss += __shfl_xor_sync(0xffffffffu, ss, o);
        if (lane == 0)
            sm[SC_OFF + r] = 22.627416997969522f / fmaxf(sqrtf(ss), 1e-12f);
    }
    // rope tables
    for (int idx = tid; idx < NTOK * 32; idx += NTHREADS) {
        float re = rotary[idx];
        sm[RC_OFF + idx] = cosf(re);
        sm[RS_OFF + idx] = sinf(re);
    }
    // zero AO pad rows 49..55 (out-proj A operand reads them)
    for (int idx = tid; idx < 7 * AO_STR; idx += NTHREADS)
        sm[AO_OFF + NTOK * AO_STR + idx] = 0.f;
    __syncthreads();

    // xs = tf32(x * gamma * sc), rows 49..55 zero  (float4 path)
    for (int idx4 = tid; idx4 < 56 * (DIMX / 4); idx4 += NTHREADS) {
        int r  = idx4 >> 7;
        int k4 = (idx4 & 127) * 4;
        float4 v = make_float4(0.f, 0.f, 0.f, 0.f);
        if (r < NTOK) {
            float sc = sm[SC_OFF + r];
            float4 xv = *(const float4*)(xw + r * DIMX + k4);
            float4 gm = *(const float4*)(gamma + k4);
            v.x = tf32f(xv.x * gm.x * sc); v.y = tf32f(xv.y * gm.y * sc);
            v.z = tf32f(xv.z * gm.z * sc); v.w = tf32f(xv.w * gm.w * sc);
        }
        *(float4*)(sm + XS_OFF + r * XS_STR + k4) = v;
    }
    __syncthreads();

    // gating g = sigmoid(xn @ w_g + b_g)
    for (int r = warp; r < NTOK; r += 16) {
        float acc[NHEAD];
        #pragma unroll
        for (int h = 0; h < NHEAD; h++) acc[h] = 0.f;
        for (int k = lane; k < DIMX; k += 32) {
            float xv = sm[XS_OFF + r * XS_STR + k];
            float4 wg0 = *(const float4*)(w_g + k * NHEAD);
            float4 wg1 = *(const float4*)(w_g + k * NHEAD + 4);
            acc[0] += xv * wg0.x; acc[1] += xv * wg0.y;
            acc[2] += xv * wg0.z; acc[3] += xv * wg0.w;
            acc[4] += xv * wg1.x; acc[5] += xv * wg1.y;
            acc[6] += xv * wg1.z; acc[7] += xv * wg1.w;
        }
        #pragma unroll
        for (int h = 0; h < NHEAD; h++) {
            #pragma unroll
            for (int o = 16; o; o >>= 1)
                acc[h] += __shfl_xor_sync(0xffffffffu, acc[h], o);
        }
        if (lane == 0) {
            #pragma unroll
            for (int h = 0; h < NHEAD; h++)
                sm[G_OFF + r * NHEAD + h] = 1.f / (1.f + __expf(-(acc[h] + b_g[h])));
        }
    }

    const float attn_scale = 0.17677669529663687f; // 32^-0.5

    // ---------------- per head: QKV mma + RoPE + attention ----------------
    for (int h = 0; h < NHEAD; h++) {
        float aq[3][4];
        #pragma unroll
        for (int f = 0; f < 3; f++)
            #pragma unroll
            for (int j = 0; j < 4; j++) aq[f][j] = 0.f;

        for (int k0 = 0; k0 < DIMX; k0 += 32) {
            __syncthreads();
            // stage B chunk [32][96]: cols 0-31 q, 32-63 k, 64-95 v of head h (tf32-rounded)
            for (int idx = tid; idx < 32 * 96; idx += NTHREADS) {
                int kk = idx / 96, c = idx % 96;
                int gcol = (c >> 5) * 256 + h * 32 + (c & 31);
                sm[BQ_OFF + kk * BQ_STR + c] = tf32f(w_qkv[(long)(k0 + kk) * QKVW + gcol]);
            }
            __syncthreads();

            #pragma unroll
            for (int ks = 0; ks < 32; ks += 8) {
                int r0 = m0 + gi;
                int ka = k0 + ks + tg;
                unsigned a0 = smu[XS_OFF + r0 * XS_STR + ka];
                unsigned a2 = smu[XS_OFF + r0 * XS_STR + ka + 4];
                unsigned a1 = 0, a3 = 0;
                if (hi_ok) {
                    a1 = smu[XS_OFF + (r0 + 8) * XS_STR + ka];
                    a3 = smu[XS_OFF + (r0 + 8) * XS_STR + ka + 4];
                }
                #pragma unroll
                for (int f = 0; f < 3; f++) {
                    int nb = nw * 24 + f * 8 + gi;
                    unsigned b0 = smu[BQ_OFF + (ks + tg) * BQ_STR + nb];
                    unsigned b1 = smu[BQ_OFF + (ks + tg + 4) * BQ_STR + nb];
                    mma8(aq[f], a0, a1, a2, a3, b0, b1);
                }
            }
        }

        // write Q/K/V tiles with in-register RoPE (C frag holds adjacent even/odd col pairs)
        #pragma unroll
        for (int f = 0; f < 3; f++) {
            int c0 = nw * 24 + f * 8 + 2 * tg;
            int s  = c0 >> 5;       // 0=q,1=k,2=v
            int d0 = c0 & 31;
            float* tp = sm + QT_OFF + s * TIL_SZ;
            #pragma unroll
            for (int half = 0; half < 2; half++) {
                int r = m0 + gi + half * 8;
                if (r < NTOK) {
                    float e = aq[f][half * 2 + 0];
                    float o = aq[f][half * 2 + 1];
                    if (s < 2) {
                        float ce = sm[RC_OFF + r * 32 + d0], se = sm[RS_OFF + r * 32 + d0];
                        float co = sm[RC_OFF + r * 32 + d0 + 1], so = sm[RS_OFF + r * 32 + d0 + 1];
                        float ne = e * ce - o * se;
                        float no = o * co + e * so;
                        e = ne; o = no;
                    }
                    tp[r * TIL_STR + d0]     = e;
                    tp[r * TIL_STR + d0 + 1] = o;
                }
            }
        }
        __syncthreads();

        // attention: warp-per-query-row (identical logic to passing scalar kernel)
        for (int i = warp; i < NTOK; i += 16) {
            int j1 = lane, j2 = lane + 32;
            int j2c = (j2 < NTOK) ? j2 : 0;
            float s1 = 0.f, s2 = 0.f;
            #pragma unroll
            for (int d = 0; d < 32; d++) {
                float qv = sm[QT_OFF + i * TIL_STR + d];
                s1 += qv * sm[KT_OFF + j1 * TIL_STR + d];
                s2 += qv * sm[KT_OFF + j2c * TIL_STR + d];
            }
            s1 *= attn_scale; s2 *= attn_scale;
            float m2v = (j2 < NTOK) ? s2 : -1e30f;
            float mx = fmaxf(s1, m2v);
            #pragma unroll
            for (int o = 16; o; o >>= 1)
                mx = fmaxf(mx, __shfl_xor_sync(0xffffffffu, mx, o));
            float e1 = __expf(s1 - mx);
            float e2 = (j2 < NTOK) ? __expf(s2 - mx) : 0.f;
            float sum = e1 + e2;
            #pragma unroll
            for (int o = 16; o; o >>= 1)
                sum += __shfl_xor_sync(0xffffffffu, sum, o);
            float inv = __fdividef(1.f, sum);
            sm[PR_OFF + warp * 52 + j1] = e1 * inv;
            if (j2 < NTOK) sm[PR_OFF + warp * 52 + j2] = e2 * inv;
            __syncwarp();
            float acc = 0.f;
            #pragma unroll 7
            for (int j = 0; j < NTOK; j++)
                acc += sm[PR_OFF + warp * 52 + j] * sm[VT_OFF + j * TIL_STR + lane];
            acc *= sm[G_OFF + i * NHEAD + h];
            sm[AO_OFF + i * AO_STR + h * 32 + lane] = tf32f(acc);
            __syncwarp();
        }
        __syncthreads();
    }

    // ---------------- out-proj: AO[64x256] @ w_out[256x512] via mma ----------------
    // w_out chunks staged over the (now dead) xs region
    float po[16][4];
    #pragma unroll
    for (int f = 0; f < 16; f++)
        #pragma unroll
        for (int j = 0; j < 4; j++) po[f][j] = 0.f;

    for (int k0 = 0; k0 < 256; k0 += 32) {
        __syncthreads();
        for (int idx4 = tid; idx4 < 32 * (DIMX / 4); idx4 += NTHREADS) {
            int kk = idx4 >> 7;
            int c4 = (idx4 & 127) * 4;
            float4 wv = *(const float4*)(w_out + (long)(k0 + kk) * DIMX + c4);
            float4 tv;
            tv.x = tf32f(wv.x); tv.y = tf32f(wv.y);
            tv.z = tf32f(wv.z); tv.w = tf32f(wv.w);
            *(float4*)(sm + kk * BO_STR + c4) = tv;
        }
        __syncthreads();

        #pragma unroll
        for (int ks = 0; ks < 32; ks += 8) {
            int r0 = m0 + gi;
            int ka = k0 + ks + tg;
            unsigned a0 = smu[AO_OFF + r0 * AO_STR + ka];
            unsigned a2 = smu[AO_OFF + r0 * AO_STR + ka + 4];
            unsigned a1 = 0, a3 = 0;
            if (hi_ok) {
                a1 = smu[AO_OFF + (r0 + 8) * AO_STR + ka];
                a3 = smu[AO_OFF + (r0 + 8) * AO_STR + ka + 4];
            }
            #pragma unroll
            for (int f = 0; f < 16; f++) {
                int nb = nw * 128 + f * 8 + gi;
                unsigned b0 = smu[(ks + tg) * BO_STR + nb];
                unsigned b1 = smu[(ks + tg + 4) * BO_STR + nb];
                mma8(po[f], a0, a1, a2, a3, b0, b1);
            }
        }
    }

    // store (float2 per row per frag, rows < 49)
    const long obase = win * (long)(NTOK * DIMX);
    {
        int r0 = m0 + gi;
        int r1 = r0 + 8;
        #pragma unroll
        for (int f = 0; f < 16; f++) {
            int col = nw * 128 + f * 8 + 2 * tg;
            if (r0 < NTOK) {
                float2 v = make_float2(po[f][0], po[f][1]);
                *(float2*)(out + obase + (long)r0 * DIMX + col) = v;
            }
            if (r1 < NTOK) {
                float2 v = make_float2(po[f][2], po[f][3]);
                *(float2*)(out + obase + (long)r1 * DIMX + col) = v;
            }
        }
    }
}

extern "C" void kernel_launch(void* const* d_in, const int* in_sizes, int n_in,
                              void* d_out, int out_size)
{
    const float* x     = (const float*)d_in[0];
    const float* rot   = (const float*)d_in[1];
    const float* gamma = (const float*)d_in[2];
    const float* w_qkv = (const float*)d_in[3];
    const float* w_g   = (const float*)d_in[4];
    const float* b_g   = (const float*)d_in[5];
    const float* w_out = (const float*)d_in[6];

    int nwin = in_sizes[0] / (NTOK * DIMX);   // 2048
    size_t smem = SMEM_FLOATS * sizeof(float);
    cudaFuncSetAttribute(fused_win_attn_tc,
                         cudaFuncAttributeMaxDynamicSharedMemorySize, (int)smem);
    fused_win_attn_tc<<<nwin, NTHREADS, smem>>>(
        x, rot, gamma, w_qkv, w_g, b_g, w_out, (float*)d_out);
}